// round 17
// baseline (speedup 1.0000x reference)
#include <cuda_runtime.h>
#include <cuda_fp16.h>
#include <cuda_bf16.h>
#include <cstdint>

#define D 128
#define NMAX 50000
#define EMAX 800000
#define D4 (D/4)    // 32 float4 per fp32 row

// ---------------- scratch (no allocations allowed) ----------------
__device__ int    g_deg[NMAX];             // raw in-degree (no self-loop)
__device__ float  g_dinv[NMAX];            // rsqrt(deg+1)
__device__ int    g_rowstart[NMAX];
__device__ int    g_cur[NMAX];
__device__ int    g_esrc[EMAX];
__device__ int    g_total;                 // CSR slot allocator
__device__ __half g_h[(size_t)NMAX * D];   // layer-1 messages (fp16, dinv-scaled)
__device__ __half g_h2[(size_t)NMAX * D];  // layer-2 messages (fp16, dinv-scaled)
// W split into bf16 hi/lo, TRANSPOSED: buf[n*128 + k] = bf16(W[k][n])
__device__ __align__(16) __nv_bfloat16 g_wh1[16384];
__device__ __align__(16) __nv_bfloat16 g_wl1[16384];
__device__ __align__(16) __nv_bfloat16 g_wh2[16384];
__device__ __align__(16) __nv_bfloat16 g_wl2[16384];

// per-block edge-index dtype detection (int64 values < 2^31 => odd words 0)
__device__ __forceinline__ int detect_is64(const int* __restrict__ ei) {
    int all0 = 1;
    for (int j = 0; j < 64; ++j)
        if (ei[2 * j + 1] != 0) { all0 = 0; break; }
    return all0;
}

__device__ __forceinline__ int load_idx(const int* __restrict__ ei, size_t pos, int is64) {
    return is64 ? ei[2 * pos] : ei[pos];
}

__device__ __forceinline__ unsigned pack_bf2(__nv_bfloat16 lo, __nv_bfloat16 hi) {
    return ((unsigned)__bfloat16_as_ushort(hi) << 16) | __bfloat16_as_ushort(lo);
}

// ------ W hi/lo conversion blocks + degree-count blocks (one launch) ------
__global__ void k_initcount(const int* __restrict__ ei,
                            const float* __restrict__ W1, const float* __restrict__ W2,
                            int E) {
    if (blockIdx.x < 128) {
        int i = blockIdx.x * 256 + threadIdx.x;     // 0..32767
        int mat = i >> 14;                          // 0: W1, 1: W2
        int idx = i & 16383;
        const float* W = mat ? W2 : W1;
        __nv_bfloat16* WH = mat ? g_wh2 : g_wh1;
        __nv_bfloat16* WL = mat ? g_wl2 : g_wl1;
        int k = idx >> 7, j = idx & 127;
        float w = W[idx];                           // W[k][j]
        __nv_bfloat16 h = __float2bfloat16_rn(w);
        __nv_bfloat16 l = __float2bfloat16_rn(w - __bfloat162float(h));
        WH[j * 128 + k] = h;                        // transposed [n][k]
        WL[j * 128 + k] = l;
        if (blockIdx.x == 0 && threadIdx.x == 0) g_total = 0;
    } else {
        __shared__ int s_is64;
        if (threadIdx.x == 0) s_is64 = detect_is64(ei);
        __syncthreads();
        int is64 = s_is64;
        int e0 = ((int)blockIdx.x - 128) * 1024 + threadIdx.x * 4;
#pragma unroll
        for (int q = 0; q < 4; ++q) {
            int e = e0 + q;
            if (e < E) atomicAdd(&g_deg[load_idx(ei, (size_t)E + e, is64)], 1);
        }
    }
}

// ---------------- parallel CSR slot allocation + dinv ---------------------
__global__ void k_alloc(int n) {
    int i    = blockIdx.x * blockDim.x + threadIdx.x;
    int lane = threadIdx.x & 31;
    int v = (i < n) ? g_deg[i] : 0;

    int pfx = v;
#pragma unroll
    for (int o = 1; o < 32; o <<= 1) {
        int t = __shfl_up_sync(0xffffffff, pfx, o);
        if (lane >= o) pfx += t;
    }
    int wtotal = __shfl_sync(0xffffffff, pfx, 31);
    int excl   = pfx - v;

    int base = 0;
    if (lane == 31) base = atomicAdd(&g_total, wtotal);
    base = __shfl_sync(0xffffffff, base, 31);

    if (i < n) {
        int run = base + excl;
        g_rowstart[i] = run;
        g_cur[i]      = run;
        g_dinv[i]     = rsqrtf((float)(v + 1));   // +1 self-loop
    }
}

// ---------------- shared GEMM pieces ----------------
#define AS 68                      // uint stride per smem row
#define SM_AH 0
#define SM_AL 4352                 // 64*68
#define SM_BH 8704
#define SM_BL 17408                // 8704 + 128*68
#define SM_UINTS 26112
#define SM_BYTES (SM_UINTS * 4)

__device__ __forceinline__ void mma_bf16(float4& d,
                                         unsigned a0, unsigned a1, unsigned a2, unsigned a3,
                                         unsigned b0, unsigned b1) {
    asm volatile(
        "mma.sync.aligned.m16n8k16.row.col.f32.bf16.bf16.f32 "
        "{%0,%1,%2,%3}, {%4,%5,%6,%7}, {%8,%9}, {%0,%1,%2,%3};"
        : "+f"(d.x), "+f"(d.y), "+f"(d.z), "+f"(d.w)
        : "r"(a0), "r"(a1), "r"(a2), "r"(a3), "r"(b0), "r"(b1));
}

__device__ __forceinline__ void copy_w_tiles(unsigned* sm,
                                             const __nv_bfloat16* __restrict__ WHT,
                                             const __nv_bfloat16* __restrict__ WLT) {
    unsigned* BH = sm + SM_BH;
    unsigned* BL = sm + SM_BL;
    const uint4* gh = (const uint4*)WHT;
    const uint4* gl = (const uint4*)WLT;
    for (int i = threadIdx.x; i < 2048; i += 256) {
        int nrow = i >> 4;
        int kk   = (i & 15) * 4;
        *(uint4*)&BH[nrow * AS + kk] = gh[i];
        *(uint4*)&BL[nrow * AS + kk] = gl[i];
    }
}

// MMA compute + dinv-scaled fp16 epilogue (A/B tiles already in smem)
__device__ __forceinline__ void gemm_compute(
        int rowBase, unsigned* sm, __half* __restrict__ C, int M) {
    unsigned* AH = sm + SM_AH;
    unsigned* AL = sm + SM_AL;
    unsigned* BH = sm + SM_BH;
    unsigned* BL = sm + SM_BL;

    int tid = threadIdx.x;
    int wid = tid >> 5, lane = tid & 31;
    int wm = wid & 1, wn = wid >> 1;
    int g = lane >> 2, tig = lane & 3;

    float4 acc[2][4];
#pragma unroll
    for (int mt = 0; mt < 2; ++mt)
#pragma unroll
        for (int nt = 0; nt < 4; ++nt) acc[mt][nt] = make_float4(0.f, 0.f, 0.f, 0.f);

#pragma unroll
    for (int ks = 0; ks < 8; ++ks) {
        int ka = ks * 8 + tig;
        unsigned ah[2][4], al[2][4];
#pragma unroll
        for (int mt = 0; mt < 2; ++mt) {
            int ar0 = (wm * 32 + mt * 16 + g) * AS;
            int ar1 = ar0 + 8 * AS;
            ah[mt][0] = AH[ar0 + ka];     ah[mt][1] = AH[ar1 + ka];
            ah[mt][2] = AH[ar0 + ka + 4]; ah[mt][3] = AH[ar1 + ka + 4];
            al[mt][0] = AL[ar0 + ka];     al[mt][1] = AL[ar1 + ka];
            al[mt][2] = AL[ar0 + ka + 4]; al[mt][3] = AL[ar1 + ka + 4];
        }
        unsigned bh[4][2], bl[4][2];
#pragma unroll
        for (int nt = 0; nt < 4; ++nt) {
            int br = (wn * 32 + nt * 8 + g) * AS + ka;
            bh[nt][0] = BH[br]; bh[nt][1] = BH[br + 4];
            bl[nt][0] = BL[br]; bl[nt][1] = BL[br + 4];
        }
#pragma unroll
        for (int mt = 0; mt < 2; ++mt)
#pragma unroll
            for (int nt = 0; nt < 4; ++nt) {
                mma_bf16(acc[mt][nt], ah[mt][0], ah[mt][1], ah[mt][2], ah[mt][3],
                         bh[nt][0], bh[nt][1]);
                mma_bf16(acc[mt][nt], al[mt][0], al[mt][1], al[mt][2], al[mt][3],
                         bh[nt][0], bh[nt][1]);
                mma_bf16(acc[mt][nt], ah[mt][0], ah[mt][1], ah[mt][2], ah[mt][3],
                         bl[nt][0], bl[nt][1]);
            }
    }

#pragma unroll
    for (int mt = 0; mt < 2; ++mt) {
        int r0 = rowBase + wm * 32 + mt * 16 + g;
        int r1 = r0 + 8;
        float s0 = (r0 < M) ? g_dinv[r0] : 0.f;
        float s1 = (r1 < M) ? g_dinv[r1] : 0.f;
#pragma unroll
        for (int nt = 0; nt < 4; ++nt) {
            int col = wn * 32 + nt * 8 + tig * 2;
            if (r0 < M)
                *(__half2*)(C + (size_t)r0 * 128 + col) =
                    __floats2half2_rn(acc[mt][nt].x * s0, acc[mt][nt].y * s0);
            if (r1 < M)
                *(__half2*)(C + (size_t)r1 * 128 + col) =
                    __floats2half2_rn(acc[mt][nt].z * s1, acc[mt][nt].w * s1);
        }
    }
}

// A-tile from global fp32 (layer 1)
__device__ __forceinline__ void load_a_tile(
        int rowBase, unsigned* sm, const float* __restrict__ A, int M) {
    unsigned* AH = sm + SM_AH;
    unsigned* AL = sm + SM_AL;
    int tid = threadIdx.x;
    int r  = tid >> 2;
    int t4 = tid & 3;
    int rg = rowBase + r;
    const float4* A4 = (const float4*)A;
#pragma unroll
    for (int i = 0; i < 8; ++i) {
        float4 v = make_float4(0.f, 0.f, 0.f, 0.f);
        if (rg < M) v = A4[(size_t)rg * 32 + t4 * 8 + i];
        __nv_bfloat16 h0 = __float2bfloat16_rn(v.x), h1 = __float2bfloat16_rn(v.y);
        __nv_bfloat16 h2 = __float2bfloat16_rn(v.z), h3 = __float2bfloat16_rn(v.w);
        __nv_bfloat16 l0 = __float2bfloat16_rn(v.x - __bfloat162float(h0));
        __nv_bfloat16 l1 = __float2bfloat16_rn(v.y - __bfloat162float(h1));
        __nv_bfloat16 l2 = __float2bfloat16_rn(v.z - __bfloat162float(h2));
        __nv_bfloat16 l3 = __float2bfloat16_rn(v.w - __bfloat162float(h3));
        int w = r * AS + t4 * 16 + i * 2;
        AH[w]     = pack_bf2(h0, h1);
        AH[w + 1] = pack_bf2(h2, h3);
        AL[w]     = pack_bf2(l0, l1);
        AL[w + 1] = pack_bf2(l2, l3);
    }
}

// ---- mega: GEMM1 (dinv-scaled), then each block fills its CSR slice ------
__global__ __launch_bounds__(256) void k_mega(
        const float* __restrict__ A,
        const __nv_bfloat16* __restrict__ WHT,
        const __nv_bfloat16* __restrict__ WLT,
        __half* __restrict__ C, int M,
        const int* __restrict__ ei, int E) {
    extern __shared__ unsigned sm[];
    __shared__ int s_is64;

    copy_w_tiles(sm, WHT, WLT);
    load_a_tile(blockIdx.x * 64, sm, A, M);
    __syncthreads();
    gemm_compute(blockIdx.x * 64, sm, C, M);

    if (threadIdx.x == 0) s_is64 = detect_is64(ei);
    __syncthreads();
    int is64 = s_is64;
    int e0 = blockIdx.x * 1024 + threadIdx.x * 4;
#pragma unroll
    for (int q = 0; q < 4; ++q) {
        int e = e0 + q;
        if (e < E) {
            int s = load_idx(ei, (size_t)e, is64);
            int d = load_idx(ei, (size_t)E + e, is64);
            int pos = atomicAdd(&g_cur[d], 1);
            g_esrc[pos] = s;
        }
    }
}

// ---------------- aggregation helpers (fp16 pairwise tree) ----------------
__device__ __forceinline__ void add_h4(float4& acc, uint2 raw) {
    __half2* ph = (__half2*)&raw;
    float2 lo = __half22float2(ph[0]);
    float2 hi = __half22float2(ph[1]);
    acc.x += lo.x; acc.y += lo.y; acc.z += hi.x; acc.w += hi.y;
}

__device__ __forceinline__ uint2 hadd2_pair(uint2 a, uint2 b) {
    __half2* pa = (__half2*)&a;
    __half2* pb = (__half2*)&b;
    uint2 r;
    *(__half2*)&r.x = __hadd2(pa[0], pb[0]);
    *(__half2*)&r.y = __hadd2(pa[1], pb[1]);
    return r;
}

// gather-sum one node's row (lane owns 4 cols). H rows pre-scaled by dinv.
__device__ __forceinline__ float4 agg_node(const uint2* __restrict__ H2,
                                           unsigned node, int lane) {
    float4 acc = make_float4(0.f, 0.f, 0.f, 0.f);
    add_h4(acc, H2[node * 32u + lane]);  // self-loop

    int p   = g_rowstart[node];
    int end = p + g_deg[node];

    for (; p + 3 < end; p += 4) {
        unsigned s0 = (unsigned)g_esrc[p],     s1 = (unsigned)g_esrc[p + 1];
        unsigned s2 = (unsigned)g_esrc[p + 2], s3 = (unsigned)g_esrc[p + 3];
        uint2 v0 = H2[s0 * 32u + lane];
        uint2 v1 = H2[s1 * 32u + lane];
        uint2 v2 = H2[s2 * 32u + lane];
        uint2 v3 = H2[s3 * 32u + lane];
        add_h4(acc, hadd2_pair(v0, v1));
        add_h4(acc, hadd2_pair(v2, v3));
    }
    if (p + 1 < end) {
        unsigned s0 = (unsigned)g_esrc[p], s1 = (unsigned)g_esrc[p + 1];
        add_h4(acc, hadd2_pair(H2[s0 * 32u + lane], H2[s1 * 32u + lane]));
        p += 2;
    }
    if (p < end) {
        unsigned s0 = (unsigned)g_esrc[p];
        add_h4(acc, H2[s0 * 32u + lane]);
    }
    return acc;
}

// ---- fused agg1 + GEMM2: block aggregates its 64 nodes into the A-tile ---
// Reads H (layer-1 messages), writes C = g_h2 (DISTINCT buffer — no aliasing).
__global__ __launch_bounds__(256) void k_aggemm(
        const __half* __restrict__ H,      // layer-1 messages (dinv-scaled)
        const float* __restrict__ b1,      // layer-1 bias
        const __nv_bfloat16* __restrict__ WHT,
        const __nv_bfloat16* __restrict__ WLT,
        __half* __restrict__ C, int M) {
    extern __shared__ unsigned sm[];
    unsigned* AH = sm + SM_AH;
    unsigned* AL = sm + SM_AL;

    copy_w_tiles(sm, WHT, WLT);

    int tid = threadIdx.x;
    int wid = tid >> 5, lane = tid & 31;
    int rowBase = blockIdx.x * 64;
    const uint2* H2 = (const uint2*)H;
    float4 bv = ((const float4*)b1)[lane];

    // aggregate 64 nodes: warp w handles rows w*8 .. w*8+7
#pragma unroll
    for (int it = 0; it < 8; ++it) {
        int r = wid * 8 + it;
        int node = rowBase + r;
        float4 o = make_float4(0.f, 0.f, 0.f, 0.f);
        if (node < M) {
            float4 acc = agg_node(H2, (unsigned)node, lane);
            float di = g_dinv[node];
            o.x = fmaxf(fmaf(di, acc.x, bv.x), 0.f);
            o.y = fmaxf(fmaf(di, acc.y, bv.y), 0.f);
            o.z = fmaxf(fmaf(di, acc.z, bv.z), 0.f);
            o.w = fmaxf(fmaf(di, acc.w, bv.w), 0.f);
        }
        // fp32 -> bf16 hi/lo straight into the MMA A-tile
        __nv_bfloat16 h0 = __float2bfloat16_rn(o.x), h1 = __float2bfloat16_rn(o.y);
        __nv_bfloat16 h2 = __float2bfloat16_rn(o.z), h3 = __float2bfloat16_rn(o.w);
        __nv_bfloat16 l0 = __float2bfloat16_rn(o.x - __bfloat162float(h0));
        __nv_bfloat16 l1 = __float2bfloat16_rn(o.y - __bfloat162float(h1));
        __nv_bfloat16 l2 = __float2bfloat16_rn(o.z - __bfloat162float(h2));
        __nv_bfloat16 l3 = __float2bfloat16_rn(o.w - __bfloat162float(h3));
        int w = r * AS + lane * 2;
        AH[w]     = pack_bf2(h0, h1);
        AH[w + 1] = pack_bf2(h2, h3);
        AL[w]     = pack_bf2(l0, l1);
        AL[w + 1] = pack_bf2(l2, l3);
    }
    __syncthreads();

    gemm_compute(rowBase, sm, C, M);
}

// ---------------- standalone aggregation (layer 2) ------------------------
__global__ void k_agg(const __half* __restrict__ H,
                      const float* __restrict__ b,
                      float* __restrict__ out, int n) {
    int warp = (int)((blockIdx.x * (size_t)blockDim.x + threadIdx.x) >> 5);
    int lane = threadIdx.x & 31;
    if (warp >= n) return;
    unsigned node = (unsigned)warp;

    const uint2* H2 = (const uint2*)H;
    float4 acc = agg_node(H2, node, lane);

    float di = g_dinv[node];
    float4 bv = ((const float4*)b)[lane];
    float4 r;
    r.x = fmaxf(fmaf(di, acc.x, bv.x), 0.f);
    r.y = fmaxf(fmaf(di, acc.y, bv.y), 0.f);
    r.z = fmaxf(fmaf(di, acc.z, bv.z), 0.f);
    r.w = fmaxf(fmaf(di, acc.w, bv.w), 0.f);
    ((float4*)out)[node * 32u + lane] = r;
}

// ---------------- launch ----------------
extern "C" void kernel_launch(void* const* d_in, const int* in_sizes, int n_in,
                              void* d_out, int out_size) {
    const float* x  = (const float*)d_in[0];
    const int*   ei = (const int*)d_in[1];
    const float* W1 = (const float*)d_in[2];
    const float* b1 = (const float*)d_in[3];
    const float* W2 = (const float*)d_in[4];
    const float* b2 = (const float*)d_in[5];
    float* out = (float*)d_out;

    int n = in_sizes[0] / D;        // 50000
    int E = in_sizes[1] / 2;        // 800000

    __half *h, *h2;  int* degPtr;
    __nv_bfloat16 *wh1, *wl1, *wh2, *wl2;
    cudaGetSymbolAddress((void**)&h,      g_h);
    cudaGetSymbolAddress((void**)&h2,     g_h2);
    cudaGetSymbolAddress((void**)&degPtr, g_deg);
    cudaGetSymbolAddress((void**)&wh1, g_wh1);
    cudaGetSymbolAddress((void**)&wl1, g_wl1);
    cudaGetSymbolAddress((void**)&wh2, g_wh2);
    cudaGetSymbolAddress((void**)&wl2, g_wl2);

    cudaFuncSetAttribute(k_mega,   cudaFuncAttributeMaxDynamicSharedMemorySize, SM_BYTES);
    cudaFuncSetAttribute(k_aggemm, cudaFuncAttributeMaxDynamicSharedMemorySize, SM_BYTES);

    int countBlocks = (E + 1023) / 1024;   // 4 edges/thread
    int aggBlocks   = (n * 32 + 255) / 256;
    int gemmBlocks  = (n + 63) / 64;       // 782
    int nodeBlocks  = (n + 255) / 256;

    // zero degrees (captured async memset)
    cudaMemsetAsync(degPtr, 0, (size_t)n * sizeof(int));
    // W hi/lo conversion blocks + degree-count blocks
    k_initcount<<<128 + countBlocks, 256>>>(ei, W1, W2, E);
    // CSR slot allocation + dinv (dinv ready BEFORE gemm1)
    k_alloc<<<nodeBlocks, 256>>>(n);
    // GEMM1 (rows pre-scaled by dinv) with per-block CSR fill tail
    k_mega<<<gemmBlocks, 256, SM_BYTES>>>(x, wh1, wl1, h, n, ei, E);
    // FUSED: layer-1 agg -> bias/ReLU -> GEMM2, output to DISTINCT buffer h2
    k_aggemm<<<gemmBlocks, 256, SM_BYTES>>>(h, b1, wh2, wl2, h2, n);
    // layer-2 aggregation (reads h2)
    k_agg<<<aggBlocks, 256>>>(h2, b2, out, n);
}